// round 2
// baseline (speedup 1.0000x reference)
#include <cuda_runtime.h>
#include <cuda_fp16.h>
#include <stdint.h>

#define DI __device__ __forceinline__
#define N_NODES 8192
#define F_IN    512
#define F_OUT   256
#define K1      1536

__device__ __align__(16) __half g_xh[(size_t)N_NODES * K1];
__device__ __align__(16) __half g_wt[(size_t)F_OUT * K1];
__device__ __align__(16) float  g_h [(size_t)N_NODES * F_OUT];
__device__ __align__(16) __half g_wht[(size_t)F_OUT * N_NODES];
__device__ __align__(16) float  g_b[N_NODES];
__device__ __align__(16) float  g_w[N_NODES];
__device__ float g_u[F_IN];
__device__ float g_c;
__device__ float g_gmax;

DI uint32_t sm_u32(const void* p){ return (uint32_t)__cvta_generic_to_shared(p); }
DI void cp16(uint32_t d, const void* s){ asm volatile("cp.async.cg.shared.global [%0],[%1],16;\n"::"r"(d),"l"(s)); }
DI void cpcommit(){ asm volatile("cp.async.commit_group;\n":::"memory"); }
DI void cpwait1(){ asm volatile("cp.async.wait_group 1;\n":::"memory"); }
DI void cpwait0(){ asm volatile("cp.async.wait_group 0;\n":::"memory"); }

DI void mma16816(float* c, const uint32_t* a, uint32_t b0, uint32_t b1){
  asm volatile("mma.sync.aligned.m16n8k16.row.col.f32.f16.f16.f32 "
    "{%0,%1,%2,%3},{%4,%5,%6,%7},{%8,%9},{%0,%1,%2,%3};\n"
    : "+f"(c[0]),"+f"(c[1]),"+f"(c[2]),"+f"(c[3])
    : "r"(a[0]),"r"(a[1]),"r"(a[2]),"r"(a[3]),"r"(b0),"r"(b1));
}

// XOR-swizzled shared tile: row length 64 halves (128B = 8 x 16B chunks),
// chunk index xored with (row & 7) -> conflict-free LDS and 16B cp.async stores.
DI uint32_t lds2(const __half* base, int row, int colh){
  int ch = colh >> 3, rem = colh & 7;
  return *(const uint32_t*)(base + row*64 + ((ch ^ (row & 7)) << 3) + rem);
}

// block tile 64(m) x 256(n) x 64(k); 8 warps = 2(m) x 4(n); warp tile 32x64
DI void mma_tile(const __half* As, const __half* Bs, float (&acc)[2][8][4],
                 int wm, int wn, int g, int tg){
#pragma unroll
  for (int kk4=0; kk4<4; kk4++){
    int kk = kk4*16 + tg*2;
    uint32_t a[2][4];
#pragma unroll
    for (int mi=0; mi<2; mi++){
      int r = wm*32 + mi*16 + g;
      a[mi][0]=lds2(As,r,kk);   a[mi][1]=lds2(As,r+8,kk);
      a[mi][2]=lds2(As,r,kk+8); a[mi][3]=lds2(As,r+8,kk+8);
    }
#pragma unroll
    for (int ni=0; ni<8; ni++){
      int rn = wn*64 + ni*8 + g;
      uint32_t b0 = lds2(Bs,rn,kk), b1 = lds2(Bs,rn,kk+8);
      mma16816(acc[0][ni], a[0], b0, b1);
      mma16816(acc[1][ni], a[1], b0, b1);
    }
  }
}

// ---------------- pre-kernels ----------------
// x split into [hi | hi | lo] along K (3-segment fp16 split GEMM)
__global__ void k_convx(const float* __restrict__ x){
  int idx = blockIdx.x*256 + threadIdx.x;
  if (idx >= N_NODES*F_IN) return;
  int j = idx >> 9, k = idx & 511;
  float v = x[idx];
  __half hi = __float2half_rn(v);
  __half lo = __float2half_rn(v - __half2float(hi));
  size_t base = (size_t)j*K1 + k;
  g_xh[base] = hi; g_xh[base+512] = hi; g_xh[base+1024] = lo;
}
// W^T segments: [W_hi | W_lo | W_hi]  => sum = x_hi*W_hi + x_hi*W_lo + x_lo*W_hi
__global__ void k_convw(const float* __restrict__ wgt){
  int idx = blockIdx.x*256 + threadIdx.x;
  if (idx >= F_IN*F_OUT) return;
  int k = idx >> 8, f = idx & 255;
  float v = wgt[idx];
  __half hi = __float2half_rn(v);
  __half lo = __float2half_rn(v - __half2float(hi));
  size_t base = (size_t)f*K1 + k;
  g_wt[base] = hi; g_wt[base+512] = lo; g_wt[base+1024] = hi;
}
// u = W @ phi_dst (fp32, one warp per k-row of W)
__global__ void k_u(const float* __restrict__ wgt, const float* __restrict__ phi){
  int warp = (blockIdx.x*256 + threadIdx.x) >> 5;
  int lane = threadIdx.x & 31;
  if (warp >= F_IN) return;
  float s = 0.f;
#pragma unroll
  for (int i=0;i<8;i++){ int f=i*32+lane; s += wgt[warp*256+f]*phi[256+f]; }
  for (int o=16;o;o>>=1) s += __shfl_down_sync(0xFFFFFFFFu, s, o);
  if (!lane) g_u[warp] = s;
}
__global__ void k_cc(const float* __restrict__ bias, const float* __restrict__ phi){
  int lane = threadIdx.x;
  float s = 0.f;
#pragma unroll
  for (int i=0;i<8;i++){ int f=i*32+lane; s += bias[f]*phi[256+f]; }
  for (int o=16;o;o>>=1) s += __shfl_down_sync(0xFFFFFFFFu, s, o);
  if (!lane) g_c = s;
}
// b = x @ u + c   (fp32 exact path: softmax weights are error-sensitive)
__global__ void k_bvec(const float* __restrict__ x){
  __shared__ float su[F_IN];
  for (int i=threadIdx.x; i<F_IN; i+=256) su[i] = g_u[i];
  __syncthreads();
  int row = blockIdx.x*8 + (threadIdx.x >> 5);
  int lane = threadIdx.x & 31;
  const float* xr = x + (size_t)row*F_IN;
  float s = 0.f;
#pragma unroll
  for (int i=0;i<16;i++){ int k=i*32+lane; s += xr[k]*su[k]; }
  for (int o=16;o;o>>=1) s += __shfl_down_sync(0xFFFFFFFFu, s, o);
  if (!lane) g_b[row] = s + g_c;
}
__global__ void k_max(){
  __shared__ float s[1024];
  int t = threadIdx.x;
  float m = -3.4e38f;
  for (int i=t; i<N_NODES; i+=1024) m = fmaxf(m, g_b[i]);
  s[t] = m; __syncthreads();
  for (int o=512;o;o>>=1){ if (t<o) s[t]=fmaxf(s[t],s[t+o]); __syncthreads(); }
  if (!t) g_gmax = s[0];
}
__global__ void k_w(){
  int i = blockIdx.x*256 + threadIdx.x;
  if (i < N_NODES) g_w[i] = expf(g_b[i] - g_gmax);
}
// wht[f][j] = fp16(w[j] * h[j][f])  (transpose via smem tile)
__global__ void k_wht(){
  __shared__ float s[32][33];
  int j0 = blockIdx.x*32, f0 = blockIdx.y*32;
  int tx = threadIdx.x & 31, ty = threadIdx.x >> 5;
#pragma unroll
  for (int q=0;q<4;q++) s[ty+8*q][tx] = g_h[(size_t)(j0+ty+8*q)*F_OUT + f0+tx];
  __syncthreads();
  float wj = g_w[j0+tx];
#pragma unroll
  for (int q=0;q<4;q++)
    g_wht[(size_t)(f0+ty+8*q)*N_NODES + j0+tx] = __float2half_rn(wj * s[tx][ty+8*q]);
}

// ---------------- GEMM1: h = xh @ wt^T + bias  (M=8192,N=256,K=1536) ----------------
__global__ void k_gemm1(const float* __restrict__ bias){
  extern __shared__ __half smem_[];
  __half* As = smem_;            // 2 * 64*64 halves
  __half* Bs = smem_ + 8192;     // 2 * 256*64 halves
  int t = threadIdx.x, bm = blockIdx.x;
  int warp = t>>5, lane = t&31, wm = warp&1, wn = warp>>1, g = lane>>2, tg = lane&3;
  float acc[2][8][4] = {};
  const int KT = K1/64;
  auto cpA = [&](int buf, int kt){
#pragma unroll
    for (int i=0;i<2;i++){
      int idx = t + i*256, row = idx>>3, c8 = idx&7;
      uint32_t d = sm_u32(As + buf*4096) + row*128 + ((c8 ^ (row&7)) << 4);
      cp16(d, g_xh + (size_t)(bm*64+row)*K1 + kt*64 + c8*8);
    }
  };
  auto cpB = [&](int buf, int kt){
    uint32_t d = sm_u32(Bs + buf*16384) + (uint32_t)t*128;
    const __half* s = g_wt + (size_t)t*K1 + kt*64;
    int sw = t & 7;
#pragma unroll
    for (int i=0;i<8;i++) cp16(d + ((i^sw)<<4), s + i*8);
  };
  cpA(0,0); cpB(0,0); cpcommit();
  for (int kt=0; kt<KT; kt++){
    int cur = kt&1, nxt = cur^1;
    __syncthreads();
    if (kt+1 < KT){ cpA(nxt,kt+1); cpB(nxt,kt+1); cpcommit(); cpwait1(); }
    else cpwait0();
    __syncthreads();
    mma_tile(As + cur*4096, Bs + cur*16384, acc, wm, wn, g, tg);
  }
#pragma unroll
  for (int mi=0; mi<2; mi++)
#pragma unroll
    for (int ni=0; ni<8; ni++){
      int r = wm*32 + mi*16 + g, c = wn*64 + ni*8 + tg*2;
      float2 bv = *(const float2*)(bias + c);
      size_t go = (size_t)(bm*64+r)*F_OUT + c;
      *(float2*)(g_h+go)         = make_float2(acc[mi][ni][0]+bv.x, acc[mi][ni][1]+bv.y);
      *(float2*)(g_h+go+8*F_OUT) = make_float2(acc[mi][ni][2]+bv.x, acc[mi][ni][3]+bv.y);
    }
}

// ---------------- GEMM2: out = relu((MASK @ wht^T) / (MASK @ w)) ----------------
__global__ void k_gemm2(const int* __restrict__ adj, float* __restrict__ out){
  extern __shared__ __half smem_[];
  __half* As = smem_;            // 2 * 64*64
  __half* Bs = smem_ + 8192;     // 2 * 256*64
  __shared__ float sred[64][16];
  __shared__ float sden[64];
  int t = threadIdx.x, bm = blockIdx.x;
  int warp = t>>5, lane = t&31, wm = warp&1, wn = warp>>1, g = lane>>2, tg = lane&3;
  float acc[2][8][4] = {};
  float dpart[4] = {0.f,0.f,0.f,0.f};
  // prologue: B tile 0 (cp.async), A ints tile 0 (LDG)
  {
    uint32_t d = sm_u32(Bs) + (uint32_t)t*128;
    const __half* s = g_wht + (size_t)t*N_NODES;
    int sw = t & 7;
#pragma unroll
    for (int i=0;i<8;i++) cp16(d + ((i^sw)<<4), s + i*8);
  }
  cpcommit();
  int4 av[4];
#pragma unroll
  for (int i=0;i<4;i++){
    int idx = t + i*256, row = idx>>4, c4 = idx&15;
    av[i] = *(const int4*)(adj + (size_t)(bm*64+row)*N_NODES + c4*4);
  }
  const int KT = N_NODES/64;
  for (int kt=0; kt<KT; kt++){
    int cur = kt&1, nxt = cur^1;
    __syncthreads();   // prior mma done with As[cur]/Bs[nxt]
    __half* Ad = As + cur*4096;
#pragma unroll
    for (int i=0;i<4;i++){
      int idx = t + i*256, row = idx>>4, c4 = idx&15;
      int gj = kt*64 + c4*4, gi = bm*64 + row;
      int4 a = av[i];
      int m0 = (a.x | (gi==gj  )) ? 1 : 0;
      int m1 = (a.y | (gi==gj+1)) ? 1 : 0;
      int m2 = (a.z | (gi==gj+2)) ? 1 : 0;
      int m3 = (a.w | (gi==gj+3)) ? 1 : 0;
      float4 wv = *(const float4*)(g_w + gj);
      dpart[i] += m0*wv.x + m1*wv.y + m2*wv.z + m3*wv.w;
      uint32_t u0 = (m0 ? 0x3C00u : 0u) | (m1 ? 0x3C000000u : 0u);
      uint32_t u1 = (m2 ? 0x3C00u : 0u) | (m3 ? 0x3C000000u : 0u);
      uint32_t hidx = row*64 + (((c4>>1) ^ (row&7)) << 3) + (c4&1)*4;
      *(uint2*)(Ad + hidx) = make_uint2(u0, u1);
    }
    if (kt+1 < KT){
      uint32_t d = sm_u32(Bs + nxt*16384) + (uint32_t)t*128;
      const __half* s = g_wht + (size_t)t*N_NODES + (kt+1)*64;
      int sw = t & 7;
#pragma unroll
      for (int i=0;i<8;i++) cp16(d + ((i^sw)<<4), s + i*8);
      cpcommit();
#pragma unroll
      for (int i=0;i<4;i++){
        int idx = t + i*256, row = idx>>4, c4 = idx&15;
        av[i] = *(const int4*)(adj + (size_t)(bm*64+row)*N_NODES + (kt+1)*64 + c4*4);
      }
      cpwait1();
    } else cpwait0();
    __syncthreads();
    mma_tile(As + cur*4096, Bs + cur*16384, acc, wm, wn, g, tg);
  }
  // fp32 denominator reduction (16 partials per row)
  __syncthreads();
#pragma unroll
  for (int i=0;i<4;i++) sred[(t>>4) + 16*i][t&15] = dpart[i];
  __syncthreads();
  if (t < 64){
    float s = 0.f;
#pragma unroll
    for (int q=0;q<16;q++) s += sred[t][q];
    sden[t] = s;
  }
  __syncthreads();
#pragma unroll
  for (int mi=0; mi<2; mi++)
#pragma unroll
    for (int ni=0; ni<8; ni++){
      int r = wm*32 + mi*16 + g, c = wn*64 + ni*8 + tg*2;
      float i0 = 1.f/sden[r], i8 = 1.f/sden[r+8];
      size_t go = (size_t)(bm*64+r)*F_OUT + c;
      *(float2*)(out+go)         = make_float2(fmaxf(acc[mi][ni][0]*i0,0.f), fmaxf(acc[mi][ni][1]*i0,0.f));
      *(float2*)(out+go+8*F_OUT) = make_float2(fmaxf(acc[mi][ni][2]*i8,0.f), fmaxf(acc[mi][ni][3]*i8,0.f));
    }
}

extern "C" void kernel_launch(void* const* d_in, const int* in_sizes, int n_in,
                              void* d_out, int out_size){
  const int*   adj  = (const int*)d_in[0];
  const float* x    = (const float*)d_in[1];
  const float* wgt  = (const float*)d_in[2];
  const float* bias = (const float*)d_in[3];
  const float* phi  = (const float*)d_in[4];
  float* out = (float*)d_out;
  cudaFuncSetAttribute(k_gemm1, cudaFuncAttributeMaxDynamicSharedMemorySize, 81920);
  cudaFuncSetAttribute(k_gemm2, cudaFuncAttributeMaxDynamicSharedMemorySize, 81920);
  k_convx<<<(N_NODES*F_IN+255)/256, 256>>>(x);
  k_convw<<<(F_IN*F_OUT+255)/256, 256>>>(wgt);
  k_u<<<F_IN/8, 256>>>(wgt, phi);
  k_cc<<<1, 32>>>(bias, phi);
  k_bvec<<<N_NODES/8, 256>>>(x);
  k_gemm1<<<128, 256, 81920>>>(bias);
  k_max<<<1, 1024>>>();
  k_w<<<N_NODES/256, 256>>>();
  k_wht<<<dim3(256,8), 256>>>();
  k_gemm2<<<128, 256, 81920>>>(adj, out);
}